// round 8
// baseline (speedup 1.0000x reference)
#include <cuda_runtime.h>
#include <math.h>

// Problem constants (fixed shapes from reference setup_inputs)
#define BATCH 4
#define NPTS  8192
#define ALPHA 1000.0f

// Serpentine 2D column grid (for sort locality only)
#define GDIM   64
#define NCOL   (GDIM * GDIM)

// Chunk structure over the sorted array
#define CHSZ    32
#define NCHUNK  (NPTS / CHSZ)        // 256
#define SUPSZ   16                   // chunks per superchunk
#define NSUPER  (NCHUNK / SUPSZ)     // 16
#define MARGIN  1e-4f

// ---------------------------------------------------------------------------
// Scratch (__device__ globals; no allocation allowed)
// arr index a: 0 = xyz1 (pred), 1 = xyz2 (gt)
// ---------------------------------------------------------------------------
__device__ float4 g_pts   [2][BATCH][NPTS];      // column-sorted (x,y,z,|p|^2)
__device__ int    g_orig  [2][BATCH][NPTS];
__device__ int    g_colid [2][BATCH][NPTS];
__device__ int    g_hist  [2][BATCH][NCOL];
__device__ int    g_start [2][BATCH][NCOL + 1];
__device__ int    g_cursor[2][BATCH][NCOL];
__device__ float4 g_cmin  [2][BATCH][NCHUNK];    // chunk AABBs
__device__ float4 g_cmax  [2][BATCH][NCHUNK];
__device__ float4 g_smin  [2][BATCH][NSUPER];    // superchunk AABBs
__device__ float4 g_smax  [2][BATCH][NSUPER];
// dir 0: queries = xyz2 (gt), refs = xyz1 (pred); dir 1: swapped
__device__ float  g_dist[2][BATCH][NPTS];
__device__ int    g_idx [2][BATCH][NPTS];
__device__ int    g_cnt [2][BATCH][NPTS];

__device__ __forceinline__ int cell_coord(float x) {
    int c = (int)floorf(x * 8.0f) + 32;
    return min(GDIM - 1, max(0, c));
}
__device__ __forceinline__ int serp_col(int cx, int cy) {
    return cx * GDIM + ((cx & 1) ? (GDIM - 1 - cy) : cy);
}

// ---------------------------------------------------------------------------
// K0: zero histograms, counts, output
// ---------------------------------------------------------------------------
__global__ void dacd_zero_kernel(float* __restrict__ out) {
    int t = blockIdx.x * blockDim.x + threadIdx.x;
    if (t < 2 * BATCH * NPTS) ((int*)g_cnt)[t] = 0;
    if (t < 2 * BATCH * NCOL) ((int*)g_hist)[t] = 0;
    if (t == 0) out[0] = 0.0f;
}

// ---------------------------------------------------------------------------
// K1: serpentine column ids + histogram
// ---------------------------------------------------------------------------
__global__ void dacd_hist_kernel(const float* __restrict__ xyz1,
                                 const float* __restrict__ xyz2) {
    int t = blockIdx.x * blockDim.x + threadIdx.x;
    if (t >= 2 * BATCH * NPTS) return;
    const int a   = t / (BATCH * NPTS);
    const int rem = t % (BATCH * NPTS);
    const int b   = rem / NPTS;
    const int j   = rem % NPTS;
    const float* src = (a == 0) ? xyz1 : xyz2;
    float x = src[((size_t)b * NPTS + j) * 3 + 0];
    float y = src[((size_t)b * NPTS + j) * 3 + 1];
    int col = serp_col(cell_coord(x), cell_coord(y));
    g_colid[a][b][j] = col;
    atomicAdd(&g_hist[a][b][col], 1);
}

// ---------------------------------------------------------------------------
// K2: exclusive scan of 4096-entry histogram per set (8 blocks x 1024 thr)
// ---------------------------------------------------------------------------
__global__ void __launch_bounds__(1024)
dacd_scan_kernel() {
    const int a = blockIdx.x >> 2;
    const int b = blockIdx.x & 3;
    const int tid = threadIdx.x;
    __shared__ int sh[1024];

    int h[4];
    int tot = 0;
    #pragma unroll
    for (int i = 0; i < 4; i++) {
        h[i] = g_hist[a][b][tid * 4 + i];
        tot += h[i];
    }
    sh[tid] = tot;
    __syncthreads();
    #pragma unroll
    for (int off = 1; off < 1024; off <<= 1) {
        int v = (tid >= off) ? sh[tid - off] : 0;
        __syncthreads();
        sh[tid] += v;
        __syncthreads();
    }
    int base = sh[tid] - tot;
    #pragma unroll
    for (int i = 0; i < 4; i++) {
        g_start [a][b][tid * 4 + i] = base;
        g_cursor[a][b][tid * 4 + i] = base;
        base += h[i];
    }
    if (tid == 1023) g_start[a][b][NCOL] = base;   // == NPTS
}

// ---------------------------------------------------------------------------
// K3: scatter points into serpentine-column-sorted order
// ---------------------------------------------------------------------------
__global__ void dacd_scatter_kernel(const float* __restrict__ xyz1,
                                    const float* __restrict__ xyz2) {
    int t = blockIdx.x * blockDim.x + threadIdx.x;
    if (t >= 2 * BATCH * NPTS) return;
    const int a   = t / (BATCH * NPTS);
    const int rem = t % (BATCH * NPTS);
    const int b   = rem / NPTS;
    const int j   = rem % NPTS;
    const float* src = (a == 0) ? xyz1 : xyz2;
    float x = src[((size_t)b * NPTS + j) * 3 + 0];
    float y = src[((size_t)b * NPTS + j) * 3 + 1];
    float z = src[((size_t)b * NPTS + j) * 3 + 2];
    int col = g_colid[a][b][j];
    int pos = atomicAdd(&g_cursor[a][b][col], 1);
    g_pts [a][b][pos] = make_float4(x, y, z, x * x + y * y + z * z);
    g_orig[a][b][pos] = j;
}

// ---------------------------------------------------------------------------
// K4: chunk + superchunk AABBs. One warp per chunk (32 pts) or superchunk
// (512 pts). 2048 + 128 = 2176 warp tasks.
// ---------------------------------------------------------------------------
__global__ void __launch_bounds__(256)
dacd_aabb_kernel() {
    const int lane = threadIdx.x & 31;
    const int w    = blockIdx.x * 8 + (threadIdx.x >> 5);

    float mnx, mny, mnz, mxx, mxy, mxz;
    if (w < 2 * BATCH * NCHUNK) {
        const int sb = w >> 8;             // 0..7
        const int ch = w & (NCHUNK - 1);
        const int a = sb >> 2, b = sb & 3;
        float4 p = g_pts[a][b][ch * CHSZ + lane];
        mnx = p.x; mny = p.y; mnz = p.z;
        mxx = p.x; mxy = p.y; mxz = p.z;
        #pragma unroll
        for (int off = 16; off > 0; off >>= 1) {
            mnx = fminf(mnx, __shfl_xor_sync(0xFFFFFFFFu, mnx, off));
            mny = fminf(mny, __shfl_xor_sync(0xFFFFFFFFu, mny, off));
            mnz = fminf(mnz, __shfl_xor_sync(0xFFFFFFFFu, mnz, off));
            mxx = fmaxf(mxx, __shfl_xor_sync(0xFFFFFFFFu, mxx, off));
            mxy = fmaxf(mxy, __shfl_xor_sync(0xFFFFFFFFu, mxy, off));
            mxz = fmaxf(mxz, __shfl_xor_sync(0xFFFFFFFFu, mxz, off));
        }
        if (lane == 0) {
            g_cmin[a][b][ch] = make_float4(mnx, mny, mnz, 0.f);
            g_cmax[a][b][ch] = make_float4(mxx, mxy, mxz, 0.f);
        }
    } else if (w < 2 * BATCH * NCHUNK + 2 * BATCH * NSUPER) {
        const int u = w - 2 * BATCH * NCHUNK;
        const int sb = u >> 4;
        const int sp = u & (NSUPER - 1);
        const int a = sb >> 2, b = sb & 3;
        mnx = mny = mnz = INFINITY;
        mxx = mxy = mxz = -INFINITY;
        #pragma unroll
        for (int i = 0; i < SUPSZ; i++) {
            float4 p = g_pts[a][b][sp * (SUPSZ * CHSZ) + i * 32 + lane];
            mnx = fminf(mnx, p.x); mny = fminf(mny, p.y); mnz = fminf(mnz, p.z);
            mxx = fmaxf(mxx, p.x); mxy = fmaxf(mxy, p.y); mxz = fmaxf(mxz, p.z);
        }
        #pragma unroll
        for (int off = 16; off > 0; off >>= 1) {
            mnx = fminf(mnx, __shfl_xor_sync(0xFFFFFFFFu, mnx, off));
            mny = fminf(mny, __shfl_xor_sync(0xFFFFFFFFu, mny, off));
            mnz = fminf(mnz, __shfl_xor_sync(0xFFFFFFFFu, mnz, off));
            mxx = fmaxf(mxx, __shfl_xor_sync(0xFFFFFFFFu, mxx, off));
            mxy = fmaxf(mxy, __shfl_xor_sync(0xFFFFFFFFu, mxy, off));
            mxz = fmaxf(mxz, __shfl_xor_sync(0xFFFFFFFFu, mxz, off));
        }
        if (lane == 0) {
            g_smin[a][b][sp] = make_float4(mnx, mny, mnz, 0.f);
            g_smax[a][b][sp] = make_float4(mxx, mxy, mxz, 0.f);
        }
    }
}

// ---------------------------------------------------------------------------
// K5: exact NN via AABB-pruned chunk scans. One warp = 32 consecutive sorted
// queries. Skip a (super)chunk iff its box-to-warp-box lower bound exceeds
// wmax (warp max of current best true distances) by MARGIN — any point inside
// has geometric d^2 >= lb > btrue + MARGIN, so its computed value (error
// << MARGIN) cannot beat the current best: exact. Scanned chunks use the
// dense fminf loop; winning chunk replayed to recover min-original-index
// among value ties (== jnp.argmin semantics).
// ---------------------------------------------------------------------------
__global__ void __launch_bounds__(256)
dacd_nn_kernel() {
    const int lane  = threadIdx.x & 31;
    const int W     = blockIdx.x * 8 + (threadIdx.x >> 5);   // 0..2047
    const int dir   = W >> 10;
    const int b     = (W >> 8) & 3;
    const int chunk = W & 255;
    const int qarr  = 1 - dir;
    const int rarr  = dir;

    const int si = chunk * 32 + lane;
    const float4 q  = g_pts [qarr][b][si];
    const int    oi = g_orig[qarr][b][si];
    const float mx = -2.0f * q.x, my = -2.0f * q.y, mz = -2.0f * q.z;

    // warp bounding box (3D)
    float wx0 = q.x, wx1 = q.x, wy0 = q.y, wy1 = q.y, wz0 = q.z, wz1 = q.z;
    #pragma unroll
    for (int off = 16; off > 0; off >>= 1) {
        wx0 = fminf(wx0, __shfl_xor_sync(0xFFFFFFFFu, wx0, off));
        wx1 = fmaxf(wx1, __shfl_xor_sync(0xFFFFFFFFu, wx1, off));
        wy0 = fminf(wy0, __shfl_xor_sync(0xFFFFFFFFu, wy0, off));
        wy1 = fmaxf(wy1, __shfl_xor_sync(0xFFFFFFFFu, wy1, off));
        wz0 = fminf(wz0, __shfl_xor_sync(0xFFFFFFFFu, wz0, off));
        wz1 = fmaxf(wz1, __shfl_xor_sync(0xFFFFFFFFu, wz1, off));
    }

    const float4* __restrict__ refs = &g_pts[rarr][b][0];

    // starting superchunk: the ref chunk covering the query's own column
    int qc = serp_col(cell_coord(q.x), cell_coord(q.y));
    int i0 = g_start[rarr][b][qc] >> 5;
    i0 = __shfl_sync(0xFFFFFFFFu, i0, 16);
    i0 = min(NCHUNK - 1, max(0, i0));
    const int super0 = i0 >> 4;

    float bestd = INFINITY;     // d' = |r|^2 - 2 q.r
    float btrue = INFINITY;     // q.w + bestd
    float wmax  = INFINITY;     // warp max of btrue
    int   bestc = i0;           // winning chunk

    auto try_super = [&](int s) {
        const float4 smn = g_smin[rarr][b][s];
        const float4 smx = g_smax[rarr][b][s];
        float dx = fmaxf(fmaxf(smn.x - wx1, wx0 - smx.x), 0.0f);
        float dy = fmaxf(fmaxf(smn.y - wy1, wy0 - smx.y), 0.0f);
        float dz = fmaxf(fmaxf(smn.z - wz1, wz0 - smx.z), 0.0f);
        float lb = dx * dx + dy * dy + dz * dz;
        if (lb > wmax + MARGIN) return;

        const int cbase = s * SUPSZ;
        #pragma unroll 1
        for (int cc = 0; cc < SUPSZ; cc++) {
            const int ch = cbase + cc;
            const float4 cmn = g_cmin[rarr][b][ch];
            const float4 cmx = g_cmax[rarr][b][ch];
            float cdx = fmaxf(fmaxf(cmn.x - wx1, wx0 - cmx.x), 0.0f);
            float cdy = fmaxf(fmaxf(cmn.y - wy1, wy0 - cmx.y), 0.0f);
            float cdz = fmaxf(fmaxf(cmn.z - wz1, wz0 - cmx.z), 0.0f);
            float clb = cdx * cdx + cdy * cdy + cdz * cdz;
            if (clb > wmax + MARGIN) continue;

            const float pre = bestd;
            const float4* p = &refs[ch * CHSZ];
            #pragma unroll 8
            for (int k = 0; k < CHSZ; k++) {
                float4 v = __ldg(&p[k]);
                float d = fmaf(mx, v.x, fmaf(my, v.y, fmaf(mz, v.z, v.w)));
                bestd = fminf(bestd, d);
            }
            const bool imp = (bestd < pre);
            if (imp) { bestc = ch; btrue = q.w + bestd; }
            if (__any_sync(0xFFFFFFFFu, imp)) {
                float m = btrue;
                #pragma unroll
                for (int off = 16; off > 0; off >>= 1)
                    m = fmaxf(m, __shfl_xor_sync(0xFFFFFFFFu, m, off));
                wmax = m;
            }
        }
    };

    try_super(super0);
    #pragma unroll 1
    for (int st = 1; st < NSUPER; st++) {
        if (super0 + st < NSUPER) try_super(super0 + st);
        if (super0 - st >= 0)     try_super(super0 - st);
    }

    // replay winning chunk: min ORIGINAL index among value ties (= jnp.argmin)
    const int base = bestc * CHSZ;
    int bj = 0x7FFFFFFF;
    #pragma unroll 8
    for (int k = 0; k < CHSZ; k++) {
        float4 v = refs[base + k];
        float d = fmaf(mx, v.x, fmaf(my, v.y, fmaf(mz, v.z, v.w)));
        if (d == bestd) bj = min(bj, g_orig[rarr][b][base + k]);
    }

    g_dist[dir][b][oi] = q.w + bestd;
    g_idx [dir][b][oi] = bj;
    atomicAdd(&g_cnt[dir][b][bj], 1);
}

// ---------------------------------------------------------------------------
// K6: density-aware weighting + reduction to scalar.
// frac_21 = 1.0 exactly; ceil(frac_21) = 1.
// weight1 = 1 / max(1/c + 1e-6, 1),  weight2 = 1 / (c + 1e-6)
// out = sum (1 - exp(-alpha*d) * w) / (2*B*N)
// ---------------------------------------------------------------------------
__global__ void __launch_bounds__(256)
dacd_loss_kernel(float* __restrict__ out) {
    const int t = blockIdx.x * blockDim.x + threadIdx.x;
    const int dir = t / (BATCH * NPTS);
    const int rem = t % (BATCH * NPTS);
    const int b = rem / NPTS;
    const int i = rem % NPTS;

    float dist = g_dist[dir][b][i];
    int   idx  = g_idx [dir][b][i];
    float c    = (float)g_cnt[dir][b][idx];

    float w;
    if (dir == 0) {
        w = 1.0f / fmaxf(1.0f / c + 1e-6f, 1.0f);
    } else {
        w = 1.0f / (c + 1e-6f);
    }

    float e = expf(-dist * ALPHA);
    float contrib = (1.0f - e * w) * (1.0f / (2.0f * BATCH * NPTS));

    #pragma unroll
    for (int off = 16; off > 0; off >>= 1)
        contrib += __shfl_down_sync(0xFFFFFFFFu, contrib, off);

    __shared__ float warp_sums[8];
    const int lane = threadIdx.x & 31;
    const int wid  = threadIdx.x >> 5;
    if (lane == 0) warp_sums[wid] = contrib;
    __syncthreads();

    if (wid == 0) {
        float s = (lane < 8) ? warp_sums[lane] : 0.0f;
        #pragma unroll
        for (int off = 4; off > 0; off >>= 1)
            s += __shfl_down_sync(0xFFFFFFFFu, s, off);
        if (lane == 0) atomicAdd(out, s);
    }
}

// ---------------------------------------------------------------------------
// Launch
// ---------------------------------------------------------------------------
extern "C" void kernel_launch(void* const* d_in, const int* in_sizes, int n_in,
                              void* d_out, int out_size) {
    const float* xyz1 = (const float*)d_in[0];  // prediction [4,8192,3]
    const float* xyz2 = (const float*)d_in[1];  // ground truth [4,8192,3]
    float* out = (float*)d_out;

    (void)in_sizes; (void)n_in; (void)out_size;

    const int total = 2 * BATCH * NPTS;          // 65536

    dacd_zero_kernel    <<<(total + 255) / 256, 256>>>(out);
    dacd_hist_kernel    <<<(total + 255) / 256, 256>>>(xyz1, xyz2);
    dacd_scan_kernel    <<<2 * BATCH, 1024>>>();
    dacd_scatter_kernel <<<(total + 255) / 256, 256>>>(xyz1, xyz2);
    dacd_aabb_kernel    <<<(2 * BATCH * (NCHUNK + NSUPER) + 7) / 8, 256>>>();

    dacd_nn_kernel<<<256, 256>>>();              // 2048 warps

    dacd_loss_kernel<<<total / 256, 256>>>(out);
}